// round 3
// baseline (speedup 1.0000x reference)
#include <cuda_runtime.h>
#include <math.h>

#define S_LEN   2048
#define BATCH   2
#define EMBED   1024
#define HEADS   16
#define HDIM    64
#define MROWS   (S_LEN * BATCH)       // 4096
#define BHEADS  (BATCH * HEADS)       // 32
#define NQKV    (3 * EMBED)           // 3072

// Scratch (allocation-free rule: __device__ globals). 4 x 16MB = 64MB.
__device__ float g_Q[BHEADS * S_LEN * HDIM];
__device__ float g_K[BHEADS * S_LEN * HDIM];
__device__ float g_V[BHEADS * S_LEN * HDIM];
__device__ float g_Attn[MROWS * EMBED];   // attention output in [S,B,E] = [m,e]

// ---------------------------------------------------------------------------
// Kernel 1: QKV projection.
// C[m,f] = sum_e X[m,e] * W[f,e] + bias[f], m in [0,4096), f in [0,3072)
// Epilogue scatters into head-major Q/K/V [b*H+h, s, d]; q gets * 0.125.
// sgemm 128x128x8, 8x8 register tiles, 256 threads.
// ---------------------------------------------------------------------------
#define GBM 128
#define GBN 128
#define GBK 8
#define GTM 8
#define GTN 8
#define GPAD 4

__global__ __launch_bounds__(256) void qkv_gemm_kernel(
    const float* __restrict__ X,      // [4096, 1024]
    const float* __restrict__ W,      // [3072, 1024]
    const float* __restrict__ bias)   // [3072]
{
    __shared__ float As[GBK][GBM + GPAD];
    __shared__ float Bs[GBK][GBN + GPAD];

    const int tid = threadIdx.x;
    const int tx  = tid % (GBN / GTN);   // 0..15
    const int ty  = tid / (GBN / GTN);   // 0..15
    const int m0  = blockIdx.y * GBM;
    const int n0  = blockIdx.x * GBN;

    // loader mapping: 128 rows x 8 cols = 1024 floats = 256 threads * float4
    const int lrow = tid / 2;            // 0..127
    const int lcol = (tid % 2) * 4;      // 0 or 4

    float acc[GTM][GTN];
#pragma unroll
    for (int i = 0; i < GTM; i++)
#pragma unroll
        for (int j = 0; j < GTN; j++) acc[i][j] = 0.f;

    for (int k0 = 0; k0 < EMBED; k0 += GBK) {
        float4 av = *(const float4*)(X + (size_t)(m0 + lrow) * EMBED + k0 + lcol);
        float4 bv = *(const float4*)(W + (size_t)(n0 + lrow) * EMBED + k0 + lcol);
        As[lcol + 0][lrow] = av.x; As[lcol + 1][lrow] = av.y;
        As[lcol + 2][lrow] = av.z; As[lcol + 3][lrow] = av.w;
        Bs[lcol + 0][lrow] = bv.x; Bs[lcol + 1][lrow] = bv.y;
        Bs[lcol + 2][lrow] = bv.z; Bs[lcol + 3][lrow] = bv.w;
        __syncthreads();

#pragma unroll
        for (int kk = 0; kk < GBK; kk++) {
            float4 a0 = *(const float4*)&As[kk][ty * GTM];
            float4 a1 = *(const float4*)&As[kk][ty * GTM + 4];
            float4 b0 = *(const float4*)&Bs[kk][tx * GTN];
            float4 b1 = *(const float4*)&Bs[kk][tx * GTN + 4];
            float a[GTM] = {a0.x, a0.y, a0.z, a0.w, a1.x, a1.y, a1.z, a1.w};
            float b[GTN] = {b0.x, b0.y, b0.z, b0.w, b1.x, b1.y, b1.z, b1.w};
#pragma unroll
            for (int i = 0; i < GTM; i++)
#pragma unroll
                for (int j = 0; j < GTN; j++) acc[i][j] += a[i] * b[j];
        }
        __syncthreads();
    }

    // Scatter epilogue
#pragma unroll
    for (int i = 0; i < GTM; i++) {
        const int m = m0 + ty * GTM + i;
        const int s = m >> 1;            // BATCH == 2
        const int b = m & 1;
#pragma unroll
        for (int j = 0; j < GTN; j++) {
            const int f = n0 + tx * GTN + j;
            float v = acc[i][j] + bias[f];
            const int which = f >> 10;   // 0=q 1=k 2=v
            const int e = f & 1023;
            const int h = e >> 6;
            const int d = e & 63;
            const size_t idx = ((size_t)(b * HEADS + h) * S_LEN + s) * HDIM + d;
            if (which == 0)      g_Q[idx] = v * 0.125f;   // 1/sqrt(64)
            else if (which == 1) g_K[idx] = v;
            else                 g_V[idx] = v;
        }
    }
}

// ---------------------------------------------------------------------------
// Kernel 2: flash attention, fp32, 1 query per thread, online softmax.
// grid = (S/128, B*H), block = 128.
// ---------------------------------------------------------------------------
#define AQB 128     // queries per block
#define AKB 64      // keys per SMEM tile

__global__ __launch_bounds__(AQB, 1) void attn_kernel()
{
    const int bh  = blockIdx.y;
    const int q0  = blockIdx.x * AQB;
    const int tid = threadIdx.x;

    const float* Qp = g_Q + (size_t)bh * S_LEN * HDIM;
    const float* Kp = g_K + (size_t)bh * S_LEN * HDIM;
    const float* Vp = g_V + (size_t)bh * S_LEN * HDIM;

    __shared__ float Ksh[AKB][HDIM];
    __shared__ float Vsh[AKB][HDIM];

    // my query row (already scaled by 0.125 in the QKV epilogue)
    float4 qv[HDIM / 4];
    {
        const float4* qr = (const float4*)(Qp + (size_t)(q0 + tid) * HDIM);
#pragma unroll
        for (int i = 0; i < HDIM / 4; i++) qv[i] = qr[i];
    }

    float acc[HDIM];
#pragma unroll
    for (int d = 0; d < HDIM; d++) acc[d] = 0.f;
    float mmax = -1e30f;
    float lsum = 0.f;

    for (int k0 = 0; k0 < S_LEN; k0 += AKB) {
        __syncthreads();
        // cooperative tile load: 64*64 floats each = 1024 float4; 128 thr x 8
        {
            const float4* ksrc = (const float4*)(Kp + (size_t)k0 * HDIM);
            const float4* vsrc = (const float4*)(Vp + (size_t)k0 * HDIM);
            float4* kdst = (float4*)&Ksh[0][0];
            float4* vdst = (float4*)&Vsh[0][0];
#pragma unroll
            for (int i = tid; i < AKB * HDIM / 4; i += AQB) {
                kdst[i] = ksrc[i];
                vdst[i] = vsrc[i];
            }
        }
        __syncthreads();

#pragma unroll 4
        for (int j = 0; j < AKB; j++) {
            const float4* kr = (const float4*)&Ksh[j][0];
            float s = 0.f;
#pragma unroll
            for (int i = 0; i < HDIM / 4; i++) {
                float4 k4 = kr[i];
                s += qv[i].x * k4.x + qv[i].y * k4.y
                   + qv[i].z * k4.z + qv[i].w * k4.w;
            }
            if (s > mmax) {               // rare after warmup (~log S times)
                float scale = __expf(mmax - s);
                lsum *= scale;
#pragma unroll
                for (int d = 0; d < HDIM; d++) acc[d] *= scale;
                mmax = s;
            }
            float p = __expf(s - mmax);
            lsum += p;
            const float4* vr = (const float4*)&Vsh[j][0];
#pragma unroll
            for (int i = 0; i < HDIM / 4; i++) {
                float4 v4 = vr[i];
                acc[4 * i + 0] += p * v4.x;
                acc[4 * i + 1] += p * v4.y;
                acc[4 * i + 2] += p * v4.z;
                acc[4 * i + 3] += p * v4.w;
            }
        }
    }

    // write to g_Attn in [m, e] layout: m = s*B + b, e = h*64 + d
    const int b = bh / HEADS;
    const int h = bh % HEADS;
    const int s_idx = q0 + tid;
    const float inv = 1.f / lsum;
    float4* outp = (float4*)(g_Attn + ((size_t)s_idx * BATCH + b) * EMBED + h * HDIM);
#pragma unroll
    for (int i = 0; i < HDIM / 4; i++) {
        float4 o;
        o.x = acc[4 * i + 0] * inv;
        o.y = acc[4 * i + 1] * inv;
        o.z = acc[4 * i + 2] * inv;
        o.w = acc[4 * i + 3] * inv;
        outp[i] = o;
    }
}

// ---------------------------------------------------------------------------
// Kernel 3: output projection.
// out[m,f] = sum_e g_Attn[m,e] * W2[f,e] + bias2[f], f in [0,1024)
// ---------------------------------------------------------------------------
__global__ __launch_bounds__(256) void out_gemm_kernel(
    const float* __restrict__ W2,     // [1024, 1024]
    const float* __restrict__ bias2,  // [1024]
    float* __restrict__ out)          // [4096, 1024]
{
    __shared__ float As[GBK][GBM + GPAD];
    __shared__ float Bs[GBK][GBN + GPAD];

    const int tid = threadIdx.x;
    const int tx  = tid % (GBN / GTN);
    const int ty  = tid / (GBN / GTN);
    const int m0  = blockIdx.y * GBM;
    const int n0  = blockIdx.x * GBN;

    const int lrow = tid / 2;
    const int lcol = (tid % 2) * 4;

    float acc[GTM][GTN];
#pragma unroll
    for (int i = 0; i < GTM; i++)
#pragma unroll
        for (int j = 0; j < GTN; j++) acc[i][j] = 0.f;

    for (int k0 = 0; k0 < EMBED; k0 += GBK) {
        float4 av = *(const float4*)(g_Attn + (size_t)(m0 + lrow) * EMBED + k0 + lcol);
        float4 bv = *(const float4*)(W2 + (size_t)(n0 + lrow) * EMBED + k0 + lcol);
        As[lcol + 0][lrow] = av.x; As[lcol + 1][lrow] = av.y;
        As[lcol + 2][lrow] = av.z; As[lcol + 3][lrow] = av.w;
        Bs[lcol + 0][lrow] = bv.x; Bs[lcol + 1][lrow] = bv.y;
        Bs[lcol + 2][lrow] = bv.z; Bs[lcol + 3][lrow] = bv.w;
        __syncthreads();

#pragma unroll
        for (int kk = 0; kk < GBK; kk++) {
            float4 a0 = *(const float4*)&As[kk][ty * GTM];
            float4 a1 = *(const float4*)&As[kk][ty * GTM + 4];
            float4 b0 = *(const float4*)&Bs[kk][tx * GTN];
            float4 b1 = *(const float4*)&Bs[kk][tx * GTN + 4];
            float a[GTM] = {a0.x, a0.y, a0.z, a0.w, a1.x, a1.y, a1.z, a1.w};
            float b[GTN] = {b0.x, b0.y, b0.z, b0.w, b1.x, b1.y, b1.z, b1.w};
#pragma unroll
            for (int i = 0; i < GTM; i++)
#pragma unroll
                for (int j = 0; j < GTN; j++) acc[i][j] += a[i] * b[j];
        }
        __syncthreads();
    }

#pragma unroll
    for (int i = 0; i < GTM; i++) {
        const int m = m0 + ty * GTM + i;
#pragma unroll
        for (int j = 0; j < GTN; j++) {
            const int f = n0 + tx * GTN + j;
            out[(size_t)m * EMBED + f] = acc[i][j] + bias2[f];
        }
    }
}

// ---------------------------------------------------------------------------
extern "C" void kernel_launch(void* const* d_in, const int* in_sizes, int n_in,
                              void* d_out, int out_size)
{
    const float* x      = (const float*)d_in[0];   // [2048, 2, 1024]
    const float* w_in   = (const float*)d_in[1];   // [3072, 1024]
    const float* b_in   = (const float*)d_in[2];   // [3072]
    const float* w_out  = (const float*)d_in[3];   // [1024, 1024]
    const float* b_out  = (const float*)d_in[4];   // [1024]
    float* out = (float*)d_out;                    // [2048, 2, 1024]

    (void)in_sizes; (void)n_in; (void)out_size;

    // 1) QKV projection + head-major scatter (+ q scaling)
    {
        dim3 grid(NQKV / GBN, MROWS / GBM);   // (24, 32)
        qkv_gemm_kernel<<<grid, 256>>>(x, w_in, b_in);
    }
    // 2) flash attention per (b,h)
    {
        dim3 grid(S_LEN / AQB, BHEADS);       // (16, 32)
        attn_kernel<<<grid, AQB>>>();
    }
    // 3) output projection -> d_out
    {
        dim3 grid(EMBED / GBN, MROWS / GBM);  // (8, 32)
        out_gemm_kernel<<<grid, 256>>>(w_out, b_out, out);
    }
}